// round 16
// baseline (speedup 1.0000x reference)
#include <cuda_runtime.h>
#include <cuda_fp16.h>

#define NB 8
#define CI 256
#define TL 1024
#define EMB 512
#define OC 256
#define NH 8
#define DH 64
#define DVH 32

// Scratch (device globals)
__device__ __half g_Wh[(EMB+EMB+OC)*CI];  // Wq ‖ Wkv rows, fp16
__device__ __half g_Woh[OC*OC];           // Wo, fp16
__device__ __half g_Qh[NB*NH*TL*DH];      // (n,h,t,64), pre-scaled by 0.125*log2(e)
__device__ __half g_Kh[NB*NH*TL*DH];      // (n,h,t,64)
__device__ __half g_Vh[NB*NH*TL*DVH];     // (n,h,t,32)
__device__ __half g_Ah[NB*OC*TL];         // attn out, interleaved [n][cpair][t][2]

// ---------------------------------------------------------------------------
__device__ __forceinline__ unsigned pack2(float lo, float hi) {
    unsigned u;
    asm("cvt.rn.f16x2.f32 %0, %2, %1;" : "=r"(u) : "f"(lo), "f"(hi));
    return u;
}

__device__ __forceinline__ float ex2(float x) {
    float r;
    asm("ex2.approx.f32 %0, %1;" : "=f"(r) : "f"(x));
    return r;
}

__device__ __forceinline__ void mma_f16(float c[4], const unsigned a[4], const unsigned b[2]) {
    asm volatile(
        "mma.sync.aligned.m16n8k16.row.col.f32.f16.f16.f32 "
        "{%0,%1,%2,%3}, {%4,%5,%6,%7}, {%8,%9}, {%0,%1,%2,%3};"
        : "+f"(c[0]), "+f"(c[1]), "+f"(c[2]), "+f"(c[3])
        : "r"(a[0]), "r"(a[1]), "r"(a[2]), "r"(a[3]),
          "r"(b[0]), "r"(b[1]));
}

__device__ __forceinline__ void ldsm_x4(unsigned& r0, unsigned& r1, unsigned& r2, unsigned& r3,
                                        unsigned addr) {
    asm volatile("ldmatrix.sync.aligned.m8n8.x4.shared.b16 {%0,%1,%2,%3}, [%4];"
                 : "=r"(r0), "=r"(r1), "=r"(r2), "=r"(r3) : "r"(addr));
}
__device__ __forceinline__ void ldsm_x4_t(unsigned& r0, unsigned& r1, unsigned& r2, unsigned& r3,
                                          unsigned addr) {
    asm volatile("ldmatrix.sync.aligned.m8n8.x4.trans.shared.b16 {%0,%1,%2,%3}, [%4];"
                 : "=r"(r0), "=r"(r1), "=r"(r2), "=r"(r3) : "r"(addr));
}

#define CP16(dst, src) \
    asm volatile("cp.async.cg.shared.global [%0], [%1], 16;" :: "r"(dst), "l"(src))
#define CP_COMMIT() asm volatile("cp.async.commit_group;")
#define CP_WAIT1()  asm volatile("cp.async.wait_group 1;")
#define CP_WAIT0()  asm volatile("cp.async.wait_group 0;")

// ---------------------------------------------------------------------------
// Prologue: fp32 -> fp16 conversion of the WEIGHTS only (x converts inline
// in qkv's B loader). 40960 + 8192 = 49152 tasks.
// ---------------------------------------------------------------------------
#define NW_TASK 40960      // (1280*256)/8
#define NO_TASK 8192       // (256*256)/8
__global__ __launch_bounds__(256) void cvt_inputs(
    const float* __restrict__ Wq, const float* __restrict__ Wkv,
    const float* __restrict__ Wo)
{
    int id = blockIdx.x * 256 + threadIdx.x;
    const float* src;
    __half* dst;
    if (id < NW_TASK) {
        int e8 = id * 8;
        src = (e8 < EMB*CI) ? (Wq + e8) : (Wkv + (e8 - EMB*CI));
        dst = g_Wh + e8;
    } else if (id < NW_TASK + NO_TASK) {
        int e8 = (id - NW_TASK) * 8;
        src = Wo + e8; dst = g_Woh + e8;
    } else return;
    float4 v0 = *(const float4*)src;
    float4 v1 = *(const float4*)(src + 4);
    uint4 w;
    w.x = pack2(v0.x, v0.y); w.y = pack2(v0.z, v0.w);
    w.z = pack2(v1.x, v1.y); w.w = pack2(v1.z, v1.w);
    *(uint4*)dst = w;
}

// ---------------------------------------------------------------------------
// QKV projection: r13 structure (K-chunks of 32, 3 bufs), but the B tile is
// loaded straight from fp32 x (LDG.128 + cvt + STS.64) — no separate x pass.
// Per buf: A 128 rows x 80 B = 10240 ; B 32 rows x 272 B = 8704 -> 18944.
// ---------------------------------------------------------------------------
#define PBUF_BYTES 18944
#define PA_BYTES 10240
#define QKV_SMEM (3*PBUF_BYTES)     // 56832
__global__ __launch_bounds__(256, 2) void qkv_mma(
    const float* __restrict__ x,
    const float* __restrict__ bq, const float* __restrict__ bkv)
{
    extern __shared__ __align__(16) unsigned char smraw[];
    const unsigned sbase = (unsigned)__cvta_generic_to_shared(smraw);
    __half* shh = (__half*)smraw;

    const int n  = blockIdx.z;
    const int m0 = blockIdx.y * 128;
    const int t0 = blockIdx.x * 128;
    const int tid = threadIdx.x;
    const int wid = tid >> 5, lane = tid & 31;
    const int g = lane >> 2, tg = lane & 3;
    const int wm = wid & 3, wn = wid >> 2;

    const __half* Wsrc = g_Wh + (size_t)m0 * CI;
    const float*  xsrc = x + (size_t)n * CI * TL + t0;

    float C[2][8][4] = {};

    // loader: A via cp.async (fp16 weights); B via fp32 LDG + inline cvt
    auto load_chunk = [&](int k0, int buf) {
        const unsigned abuf = sbase + buf*PBUF_BYTES;
        unsigned char* bptr = smraw + buf*PBUF_BYTES + PA_BYTES;
        #pragma unroll
        for (int l = 0; l < 2; l++) {
            int slot = tid + l*256;
            int m = slot >> 2, cc = slot & 3;
            CP16(abuf + m*80 + cc*16, Wsrc + (size_t)m*CI + k0 + cc*8);
        }
        CP_COMMIT();
        // B: 32 k-rows x 128 t fp32 -> fp16 rows (272 B stride); 1024 tasks
        #pragma unroll
        for (int p = 0; p < 2; p++) {
            int s0 = tid + (2*p  )*256;
            int s1 = tid + (2*p+1)*256;
            int k0r = s0 >> 5, t0q = s0 & 31;
            int k1r = s1 >> 5, t1q = s1 & 31;
            float4 v0 = *(const float4*)(xsrc + (size_t)(k0 + k0r)*TL + t0q*4);
            float4 v1 = *(const float4*)(xsrc + (size_t)(k0 + k1r)*TL + t1q*4);
            uint2 w0, w1;
            w0.x = pack2(v0.x, v0.y); w0.y = pack2(v0.z, v0.w);
            w1.x = pack2(v1.x, v1.y); w1.y = pack2(v1.z, v1.w);
            *(uint2*)(bptr + k0r*272 + t0q*8) = w0;
            *(uint2*)(bptr + k1r*272 + t1q*8) = w1;
        }
    };

    load_chunk(0, 0);
    load_chunk(32, 1);

    const int lq  = (lane >> 3) & 1;
    const int lid8 = lane & 7;
    const int lhi = lane >> 4;

    for (int c = 0; c < 8; c++) {
        if (c < 7) { CP_WAIT1(); } else { CP_WAIT0(); }
        __syncthreads();
        if (c + 2 < 8) load_chunk((c+2)*32, (c+2) % 3);
        const unsigned abuf = sbase + (c % 3)*PBUF_BYTES;
        const unsigned bbuf = abuf + PA_BYTES;
        #pragma unroll
        for (int kc = 0; kc < 2; kc++) {
            unsigned a[2][4];
            #pragma unroll
            for (int i = 0; i < 2; i++) {
                int row = wm*32 + i*16 + lq*8 + lid8;
                ldsm_x4(a[i][0], a[i][1], a[i][2], a[i][3],
                        abuf + row*80 + kc*32 + lhi*16);
            }
            unsigned b[8][2];
            #pragma unroll
            for (int jj = 0; jj < 4; jj++) {
                int krow = kc*16 + lq*8 + lid8;
                int ncol = wn*64 + (jj*2 + lhi)*8;
                ldsm_x4_t(b[2*jj][0], b[2*jj][1], b[2*jj+1][0], b[2*jj+1][1],
                          bbuf + krow*272 + ncol*2);
            }
            #pragma unroll
            for (int i = 0; i < 2; i++)
                #pragma unroll
                for (int j = 0; j < 8; j++)
                    mma_f16(C[i][j], a[i], b[j]);
        }
    }
    __syncthreads();

    const float* bias = (m0 < EMB) ? (bq + m0) : (bkv + (m0 - EMB));
    const int kind = (m0 < EMB) ? 0 : (m0 < 2*EMB) ? 1 : 2;
    // Q carries 1/sqrt(dk) * log2(e) so softmax can use raw exp2
    const float scale = (kind == 0) ? 0.125f * 1.44269504089f : 1.0f;
    {
        float br[2][2];
        #pragma unroll
        for (int i = 0; i < 2; i++) {
            br[i][0] = bias[wm*32 + i*16 + g];
            br[i][1] = bias[wm*32 + i*16 + g + 8];
        }
        #pragma unroll
        for (int i = 0; i < 2; i++)
            #pragma unroll
            for (int j = 0; j < 8; j++)
                #pragma unroll
                for (int v = 0; v < 4; v++) {
                    int ml = wm*32 + i*16 + g + ((v >> 1) << 3);
                    int tl = wn*64 + j*8 + tg*2 + (v & 1);
                    shh[tl*136 + ml] = __float2half_rn((C[i][j][v] + br[i][v>>1]) * scale);
                }
    }
    __syncthreads();

    #pragma unroll
    for (int r = 0; r < 8; r++) {
        int idx = r*256 + tid;
        int t = idx >> 4, mq = (idx & 15) * 8;
        uint4 w = *(const uint4*)&shh[t*136 + mq];
        int tgl = t0 + t;
        if (kind == 0) {
            int o = m0 + mq, h = o >> 6, d = o & 63;
            *(uint4*)&g_Qh[(((size_t)n*NH + h)*TL + tgl)*DH + d] = w;
        } else if (kind == 1) {
            int oo = m0 - EMB + mq, h = oo >> 6, d = oo & 63;
            *(uint4*)&g_Kh[(((size_t)n*NH + h)*TL + tgl)*DH + d] = w;
        } else {
            int oo = m0 - 2*EMB + mq, h = oo >> 5, d = oo & 31;
            *(uint4*)&g_Vh[(((size_t)n*NH + h)*TL + tgl)*DVH + d] = w;
        }
    }
}

// ---------------------------------------------------------------------------
// Attention (round-13 best, unchanged): cp.async 3-buf K/V pipeline,
// ldmatrix fragments, exp2-domain softmax, Q overlays the KV buffers.
// ---------------------------------------------------------------------------
#define AKV_BYTES 14336
#define AKV_OFF(buf) ((buf)*AKV_BYTES)
#define ATTN_SMEM (3*AKV_BYTES)      // 43008
__global__ __launch_bounds__(128) void attn_mma8()
{
    extern __shared__ __align__(16) unsigned char smraw[];
    const unsigned sbase = (unsigned)__cvta_generic_to_shared(smraw);

    const int qtile = 7 - blockIdx.x;   // heavy tiles first
    const int nh    = blockIdx.y;
    const int tid = threadIdx.x;
    const int wid = tid >> 5, lane = tid & 31;
    const int g = lane >> 2, tg = lane & 3;
    const int r8 = lane & 7, blk = lane >> 3;

    const __half* Qb = g_Qh + ((size_t)nh*TL + qtile*128) * DH;
    const __half* Kb = g_Kh + (size_t)nh*TL*DH;
    const __half* Vb = g_Vh + (size_t)nh*TL*DVH;

    // ---- Q tile into smem (overlaps the future KV buffers) ----
    #pragma unroll
    for (int l = 0; l < 8; l++) {
        int slot = tid + l*128;
        int row = slot >> 3, cc = slot & 7;
        CP16(sbase + row*144 + cc*16, Qb + (size_t)row*DH + cc*8);
    }
    CP_COMMIT();
    CP_WAIT0();
    __syncthreads();

    // ---- Q fragments via ldmatrix ----
    unsigned Aq[2][4][4];
    #pragma unroll
    for (int i = 0; i < 2; i++) {
        const int r0 = wid*32 + i*16;
        #pragma unroll
        for (int ks = 0; ks < 4; ks++) {
            ldsm_x4(Aq[i][ks][0], Aq[i][ks][1], Aq[i][ks][2], Aq[i][ks][3],
                    sbase + (r0 + (blk&1)*8 + r8)*144 + ks*32 + (blk>>1)*16);
        }
    }
    __syncthreads();   // all warps done reading Q -> smem reusable

    auto load_kv = [&](int j, int buf) {
        const unsigned kb_ = sbase + AKV_OFF(buf);
        const unsigned vb_ = kb_ + 9216;
        const __half* Kt = Kb + (size_t)j*64*DH;
        #pragma unroll
        for (int l = 0; l < 4; l++) {
            int slot = tid + l*128;
            int row = slot >> 3, cc = slot & 7;
            CP16(kb_ + row*144 + cc*16, Kt + (size_t)row*DH + cc*8);
        }
        const __half* Vt = Vb + (size_t)j*64*DVH;
        #pragma unroll
        for (int l = 0; l < 2; l++) {
            int slot = tid + l*128;
            int row = slot >> 2, cc = slot & 3;
            CP16(vb_ + row*80 + cc*16, Vt + (size_t)row*DVH + cc*8);
        }
        CP_COMMIT();
    };

    const int jmax = 2*qtile + 1;
    load_kv(0, 0);
    load_kv(1, 1);

    float mr[2][2] = {{-1e30f,-1e30f},{-1e30f,-1e30f}};
    float lr[2][2] = {{0,0},{0,0}};
    float O[2][4][4] = {};

    for (int j = 0; j <= jmax; j++) {
        if (j < jmax) { CP_WAIT1(); } else { CP_WAIT0(); }
        __syncthreads();
        if (j + 2 <= jmax) load_kv(j+2, (j+2) % 3);
        const unsigned kb_ = sbase + AKV_OFF(j % 3);
        const unsigned vb_ = kb_ + 9216;

        // ---- S = Q K^T (log2-domain scores) ----
        float S[2][8][4] = {};
        #pragma unroll
        for (int ks = 0; ks < 4; ks++) {
            unsigned b[8][2];
            #pragma unroll
            for (int np = 0; np < 4; np++) {
                ldsm_x4(b[2*np][0], b[2*np][1], b[2*np+1][0], b[2*np+1][1],
                        kb_ + ((np*2 + (blk>>1))*8 + r8)*144 + ks*32 + (blk&1)*16);
            }
            #pragma unroll
            for (int i = 0; i < 2; i++)
                #pragma unroll
                for (int nt = 0; nt < 8; nt++)
                    mma_f16(S[i][nt], Aq[i][ks], b[nt]);
        }

        // ---- causal mask (near diagonal only) ----
        if (j >= 2*qtile) {
            #pragma unroll
            for (int i = 0; i < 2; i++) {
                const int gr0 = qtile*128 + wid*32 + i*16 + g;
                const int gr1 = gr0 + 8;
                #pragma unroll
                for (int nt = 0; nt < 8; nt++) {
                    const int gc = j*64 + nt*8 + tg*2;
                    if (gc   > gr0) S[i][nt][0] = -1e30f;
                    if (gc+1 > gr0) S[i][nt][1] = -1e30f;
                    if (gc   > gr1) S[i][nt][2] = -1e30f;
                    if (gc+1 > gr1) S[i][nt][3] = -1e30f;
                }
            }
        }

        // ---- online softmax in exp2 domain ----
        #pragma unroll
        for (int i = 0; i < 2; i++) {
            float mx0 = -1e30f, mx1 = -1e30f;
            #pragma unroll
            for (int nt = 0; nt < 8; nt++) {
                mx0 = fmaxf(mx0, fmaxf(S[i][nt][0], S[i][nt][1]));
                mx1 = fmaxf(mx1, fmaxf(S[i][nt][2], S[i][nt][3]));
            }
            mx0 = fmaxf(mx0, __shfl_xor_sync(0xffffffffu, mx0, 1));
            mx0 = fmaxf(mx0, __shfl_xor_sync(0xffffffffu, mx0, 2));
            mx1 = fmaxf(mx1, __shfl_xor_sync(0xffffffffu, mx1, 1));
            mx1 = fmaxf(mx1, __shfl_xor_sync(0xffffffffu, mx1, 2));
            const float mn0 = fmaxf(mr[i][0], mx0), mn1 = fmaxf(mr[i][1], mx1);
            const float al0 = ex2(mr[i][0] - mn0), al1 = ex2(mr[i][1] - mn1);
            float ps0 = 0.0f, ps1 = 0.0f;
            #pragma unroll
            for (int nt = 0; nt < 8; nt++) {
                S[i][nt][0] = ex2(S[i][nt][0] - mn0); ps0 += S[i][nt][0];
                S[i][nt][1] = ex2(S[i][nt][1] - mn0); ps0 += S[i][nt][1];
                S[i][nt][2] = ex2(S[i][nt][2] - mn1); ps1 += S[i][nt][2];
                S[i][nt][3] = ex2(S[i][nt][3] - mn1); ps1 += S[i][nt][3];
            }
            ps0 += __shfl_xor_sync(0xffffffffu, ps0, 1);
            ps0 += __shfl_xor_sync(0xffffffffu, ps0, 2);
            ps1 += __shfl_xor_sync(0xffffffffu, ps1, 1);
            ps1 += __shfl_xor_sync(0xffffffffu, ps1, 2);
            lr[i][0] = lr[i][0]*al0 + ps0;  mr[i][0] = mn0;
            lr[i][1] = lr[i][1]*al1 + ps1;  mr[i][1] = mn1;
            #pragma unroll
            for (int nt = 0; nt < 4; nt++) {
                O[i][nt][0] *= al0; O[i][nt][1] *= al0;
                O[i][nt][2] *= al1; O[i][nt][3] *= al1;
            }
        }

        // ---- O += P V (V b-frags via ldsm.x4.trans, rows = s dim) ----
        #pragma unroll
        for (int kt = 0; kt < 4; kt++) {
            unsigned bv[4][2];
            #pragma unroll
            for (int np = 0; np < 2; np++) {
                ldsm_x4_t(bv[2*np][0], bv[2*np][1], bv[2*np+1][0], bv[2*np+1][1],
                          vb_ + (kt*16 + (blk&1)*8 + r8)*80 + (np*2 + (blk>>1))*16);
            }
            #pragma unroll
            for (int i = 0; i < 2; i++) {
                unsigned a[4];
                a[0] = pack2(S[i][2*kt  ][0], S[i][2*kt  ][1]);
                a[1] = pack2(S[i][2*kt  ][2], S[i][2*kt  ][3]);
                a[2] = pack2(S[i][2*kt+1][0], S[i][2*kt+1][1]);
                a[3] = pack2(S[i][2*kt+1][2], S[i][2*kt+1][3]);
                #pragma unroll
                for (int nt = 0; nt < 4; nt++)
                    mma_f16(O[i][nt], a, bv[nt]);
            }
        }
    }

    // ---- normalize + store to g_Ah interleaved [n][cpair][t][2] ----
    const int n = nh >> 3, h = nh & 7;
    unsigned* gA2 = (unsigned*)g_Ah;
    #pragma unroll
    for (int i = 0; i < 2; i++) {
        const float inv0 = 1.0f / lr[i][0], inv1 = 1.0f / lr[i][1];
        const int t_lo = qtile*128 + wid*32 + i*16 + g;
        const int t_hi = t_lo + 8;
        #pragma unroll
        for (int nt = 0; nt < 4; nt++) {
            int chp = h*16 + nt*4 + tg;
            gA2[((size_t)n*128 + chp)*TL + t_lo] = pack2(O[i][nt][0]*inv0, O[i][nt][1]*inv0);
            gA2[((size_t)n*128 + chp)*TL + t_hi] = pack2(O[i][nt][2]*inv1, O[i][nt][3]*inv1);
        }
    }
}

// ---------------------------------------------------------------------------
// Output projection (round-13 best, unchanged): CTA 128x64, warp 32x32,
// 256 CTAs, direct float2 epilogue.
// ---------------------------------------------------------------------------
#define OPA_BYTES 10240               // A: 128 rows x 80 B
#define OB_BYTES 4608                 // B: 16 * 288
#define OPBUF_BYTES (OPA_BYTES + OB_BYTES)   // 14848
#define OPROJ_SMEM (3*OPBUF_BYTES)    // 44544
__global__ __launch_bounds__(256) void oproj_mma(
    const float* __restrict__ bo, float* __restrict__ out)
{
    extern __shared__ __align__(16) unsigned char smraw[];
    const unsigned sbase = (unsigned)__cvta_generic_to_shared(smraw);

    const int n  = blockIdx.z;
    const int m0 = blockIdx.y * 128;
    const int t0 = blockIdx.x * 64;
    const int tid = threadIdx.x;
    const int wid = tid >> 5, lane = tid & 31;
    const int g = lane >> 2, tg = lane & 3;
    const int wm = wid & 3, wn = wid >> 2;   // warp: rows wm*32, cols wn*32

    const __half* Wsrc = g_Woh + (size_t)m0 * OC;
    const __half* Absrc = g_Ah + (size_t)n * 2*128*TL;   // halves [cpair][t][2]

    float C[2][4][4] = {};

    auto load_chunk = [&](int k0, int buf) {
        const unsigned abuf = sbase + buf*OPBUF_BYTES;
        const unsigned bbuf = abuf + OPA_BYTES;
        #pragma unroll
        for (int l = 0; l < 2; l++) {
            int slot = tid + l*256;
            int m = slot >> 2, cc = slot & 3;
            CP16(abuf + m*80 + cc*16, Wsrc + (size_t)m*OC + k0 + cc*8);
        }
        // B: 16 cpair rows x 256 B/row = 16 tasks/row, 256 total
        {
            int kp = tid >> 4, cc = tid & 15;
            CP16(bbuf + kp*288 + cc*16,
                 Absrc + ((size_t)((k0 >> 1) + kp)*TL + t0 + cc*4)*2);
        }
        CP_COMMIT();
    };

    load_chunk(0, 0);
    load_chunk(32, 1);

    const int lq = (lane >> 3) & 1;
    const int lid8 = lane & 7;
    const int lhi = lane >> 4;

    for (int c = 0; c < 8; c++) {
        if (c < 7) { CP_WAIT1(); } else { CP_WAIT0(); }
        __syncthreads();
        if (c + 2 < 8) load_chunk((c+2)*32, (c+2) % 3);
        const unsigned abuf = sbase + (c % 3)*OPBUF_BYTES;
        const unsigned* B_ = (const unsigned*)(smraw + (c % 3)*OPBUF_BYTES + OPA_BYTES);
        #pragma unroll
        for (int kc = 0; kc < 2; kc++) {
            unsigned a[2][4];
            #pragma unroll
            for (int i = 0; i < 2; i++) {
                int row = wm*32 + i*16 + lq*8 + lid8;
                ldsm_x4(a[i][0], a[i][1], a[i][2], a[i][3],
                        abuf + row*80 + kc*32 + lhi*16);
            }
            unsigned b[4][2];
            #pragma unroll
            for (int j = 0; j < 4; j++) {
                int col = wn*32 + j*8 + g;
                b[j][0] = B_[(kc*8 + tg  )*72 + col];
                b[j][1] = B_[(kc*8 + tg+4)*72 + col];
            }
            #pragma unroll
            for (int i = 0; i < 2; i++)
                #pragma unroll
                for (int j = 0; j < 4; j++)
                    mma_f16(C[i][j], a[i], b[j]);
        }
    }

    // ---- epilogue: direct float2 stores (coalesced 32B per quad-row) ----
    #pragma unroll
    for (int i = 0; i < 2; i++) {
        const int r_lo = m0 + wm*32 + i*16 + g;
        const int r_hi = r_lo + 8;
        const float b_lo = bo[r_lo], b_hi = bo[r_hi];
        #pragma unroll
        for (int j = 0; j < 4; j++) {
            const int tcol = t0 + wn*32 + j*8 + tg*2;
            float2 v0 = { C[i][j][0] + b_lo, C[i][j][1] + b_lo };
            float2 v1 = { C[i][j][2] + b_hi, C[i][j][3] + b_hi };
            *(float2*)(out + ((size_t)n*OC + r_lo)*TL + tcol) = v0;
            *(float2*)(out + ((size_t)n*OC + r_hi)*TL + tcol) = v1;
        }
    }
}

// ---------------------------------------------------------------------------
extern "C" void kernel_launch(void* const* d_in, const int* in_sizes, int n_in,
                              void* d_out, int out_size)
{
    const float* x   = (const float*)d_in[0];
    const float* Wq  = (const float*)d_in[1];
    const float* bq  = (const float*)d_in[2];
    const float* Wkv = (const float*)d_in[3];
    const float* bkv = (const float*)d_in[4];
    const float* Wo  = (const float*)d_in[5];
    const float* bo  = (const float*)d_in[6];
    float* out = (float*)d_out;

    cudaFuncSetAttribute(qkv_mma,
                         cudaFuncAttributeMaxDynamicSharedMemorySize, QKV_SMEM);
    cudaFuncSetAttribute(attn_mma8,
                         cudaFuncAttributeMaxDynamicSharedMemorySize, ATTN_SMEM);
    cudaFuncSetAttribute(oproj_mma,
                         cudaFuncAttributeMaxDynamicSharedMemorySize, OPROJ_SMEM);

    // 0) fp32 -> fp16 conversion of weights only (x converts inline in qkv)
    cvt_inputs<<<192, 256>>>(Wq, Wkv, Wo);

    // 1) QKV: M=1280 (10 tiles of 128), N=1024 (8 tiles of 128), per batch
    qkv_mma<<<dim3(8, 10, NB), 256, QKV_SMEM>>>(x, bq, bkv);

    // 2) flash attention: 8 Q-tiles of 128 rows, 64 (n,h) pairs
    attn_mma8<<<dim3(8, 64), 128, ATTN_SMEM>>>();

    // 3) O proj: M=256 (2 tiles of 128), N=1024 (16 tiles of 64), per batch
    oproj_mma<<<dim3(16, 2, NB), 256, OPROJ_SMEM>>>(bo, out);
}

// round 17
// speedup vs baseline: 1.0549x; 1.0549x over previous
#include <cuda_runtime.h>
#include <cuda_fp16.h>

#define NB 8
#define CI 256
#define TL 1024
#define EMB 512
#define OC 256
#define NH 8
#define DH 64
#define DVH 32

// Scratch (device globals)
__device__ __half g_Wh[(EMB+EMB+OC)*CI];  // Wq ‖ Wkv rows, fp16
__device__ __half g_xh[NB*CI*TL];         // x, fp16
__device__ __half g_Woh[OC*OC];           // Wo, fp16
__device__ __half g_Qh[NB*NH*TL*DH];      // (n,h,t,64), pre-scaled by 0.125*log2(e)
__device__ __half g_Kh[NB*NH*TL*DH];      // (n,h,t,64)
__device__ __half g_Vh[NB*NH*TL*DVH];     // (n,h,t,32)
__device__ __half g_Ah[NB*OC*TL];         // attn out, interleaved [n][cpair][t][2]

// ---------------------------------------------------------------------------
__device__ __forceinline__ unsigned pack2(float lo, float hi) {
    unsigned u;
    asm("cvt.rn.f16x2.f32 %0, %2, %1;" : "=r"(u) : "f"(lo), "f"(hi));
    return u;
}

__device__ __forceinline__ float ex2(float x) {
    float r;
    asm("ex2.approx.f32 %0, %1;" : "=f"(r) : "f"(x));
    return r;
}

__device__ __forceinline__ void mma_f16(float c[4], const unsigned a[4], const unsigned b[2]) {
    asm volatile(
        "mma.sync.aligned.m16n8k16.row.col.f32.f16.f16.f32 "
        "{%0,%1,%2,%3}, {%4,%5,%6,%7}, {%8,%9}, {%0,%1,%2,%3};"
        : "+f"(c[0]), "+f"(c[1]), "+f"(c[2]), "+f"(c[3])
        : "r"(a[0]), "r"(a[1]), "r"(a[2]), "r"(a[3]),
          "r"(b[0]), "r"(b[1]));
}

__device__ __forceinline__ void ldsm_x4(unsigned& r0, unsigned& r1, unsigned& r2, unsigned& r3,
                                        unsigned addr) {
    asm volatile("ldmatrix.sync.aligned.m8n8.x4.shared.b16 {%0,%1,%2,%3}, [%4];"
                 : "=r"(r0), "=r"(r1), "=r"(r2), "=r"(r3) : "r"(addr));
}
__device__ __forceinline__ void ldsm_x4_t(unsigned& r0, unsigned& r1, unsigned& r2, unsigned& r3,
                                          unsigned addr) {
    asm volatile("ldmatrix.sync.aligned.m8n8.x4.trans.shared.b16 {%0,%1,%2,%3}, [%4];"
                 : "=r"(r0), "=r"(r1), "=r"(r2), "=r"(r3) : "r"(addr));
}

#define CP16(dst, src) \
    asm volatile("cp.async.cg.shared.global [%0], [%1], 16;" :: "r"(dst), "l"(src))
#define CP_COMMIT() asm volatile("cp.async.commit_group;")
#define CP_WAIT1()  asm volatile("cp.async.wait_group 1;")
#define CP_WAIT0()  asm volatile("cp.async.wait_group 0;")

// ---------------------------------------------------------------------------
// Prologue: fp32 -> fp16 conversion of x, W matrices (round-13 version).
// ---------------------------------------------------------------------------
#define NW_TASK 40960      // (1280*256)/8
#define NX_TASK 262144     // (8*256*1024)/8
#define NO_TASK 8192       // (256*256)/8
__global__ __launch_bounds__(256) void cvt_inputs(
    const float* __restrict__ Wq, const float* __restrict__ Wkv,
    const float* __restrict__ x,  const float* __restrict__ Wo)
{
    int id = blockIdx.x * 256 + threadIdx.x;
    const float* src;
    __half* dst;
    if (id < NW_TASK) {
        int e8 = id * 8;
        src = (e8 < EMB*CI) ? (Wq + e8) : (Wkv + (e8 - EMB*CI));
        dst = g_Wh + e8;
    } else if (id < NW_TASK + NX_TASK) {
        int e8 = (id - NW_TASK) * 8;
        src = x + e8;  dst = g_xh + e8;
    } else if (id < NW_TASK + NX_TASK + NO_TASK) {
        int e8 = (id - NW_TASK - NX_TASK) * 8;
        src = Wo + e8; dst = g_Woh + e8;
    } else return;
    float4 v0 = *(const float4*)src;
    float4 v1 = *(const float4*)(src + 4);
    uint4 w;
    w.x = pack2(v0.x, v0.y); w.y = pack2(v0.z, v0.w);
    w.z = pack2(v1.x, v1.y); w.w = pack2(v1.z, v1.w);
    *(uint4*)dst = w;
}

// ---------------------------------------------------------------------------
// QKV projection: CTA 64(M) x 128(N), 128 threads (4 warps of 32x64),
// K-chunks of 32, cp.async 3-buf pipeline -> 4 CTAs/SM (16K regs/CTA).
// Per buf: A 64 rows x 80 B = 5120 ; B 32 rows x 272 B = 8704 -> 13824.
// ---------------------------------------------------------------------------
#define PBUF_BYTES 13824
#define PA_BYTES 5120
#define QKV_SMEM (3*PBUF_BYTES)     // 41472
__global__ __launch_bounds__(128, 4) void qkv_mma(
    const float* __restrict__ bq, const float* __restrict__ bkv)
{
    extern __shared__ __align__(16) unsigned char smraw[];
    const unsigned sbase = (unsigned)__cvta_generic_to_shared(smraw);
    __half* shh = (__half*)smraw;

    const int n  = blockIdx.z;
    const int m0 = blockIdx.y * 64;
    const int t0 = blockIdx.x * 128;
    const int tid = threadIdx.x;
    const int wid = tid >> 5, lane = tid & 31;
    const int g = lane >> 2, tg = lane & 3;
    const int wm = wid & 1, wn = wid >> 1;   // warp: rows wm*32, cols wn*64

    const __half* Wsrc = g_Wh + (size_t)m0 * CI;
    const __half* xsrc = g_xh + (size_t)n * CI * TL + t0;

    float C[2][8][4] = {};

    auto load_chunk = [&](int k0, int buf) {
        const unsigned abuf = sbase + buf*PBUF_BYTES;
        const unsigned bbuf = abuf + PA_BYTES;
        // A: 64 m-rows x 64 B (32 halves) -> 256 tasks of 16 B
        #pragma unroll
        for (int l = 0; l < 2; l++) {
            int slot = tid + l*128;
            int m = slot >> 2, cc = slot & 3;
            CP16(abuf + m*80 + cc*16, Wsrc + (size_t)m*CI + k0 + cc*8);
        }
        // B: 32 k-rows x 256 B (128 halves) -> 512 tasks of 16 B
        #pragma unroll
        for (int l = 0; l < 4; l++) {
            int slot = tid + l*128;
            int k = slot >> 4, cc = slot & 15;
            CP16(bbuf + k*272 + cc*16, xsrc + (size_t)(k0+k)*TL + cc*8);
        }
        CP_COMMIT();
    };

    load_chunk(0, 0);
    load_chunk(32, 1);

    const int lq  = (lane >> 3) & 1;
    const int lid8 = lane & 7;
    const int lhi = lane >> 4;

    for (int c = 0; c < 8; c++) {
        if (c < 7) { CP_WAIT1(); } else { CP_WAIT0(); }
        __syncthreads();
        if (c + 2 < 8) load_chunk((c+2)*32, (c+2) % 3);
        const unsigned abuf = sbase + (c % 3)*PBUF_BYTES;
        const unsigned bbuf = abuf + PA_BYTES;
        #pragma unroll
        for (int kc = 0; kc < 2; kc++) {
            unsigned a[2][4];
            #pragma unroll
            for (int i = 0; i < 2; i++) {
                int row = wm*32 + i*16 + lq*8 + lid8;
                ldsm_x4(a[i][0], a[i][1], a[i][2], a[i][3],
                        abuf + row*80 + kc*32 + lhi*16);
            }
            unsigned b[8][2];
            #pragma unroll
            for (int jj = 0; jj < 4; jj++) {
                int krow = kc*16 + lq*8 + lid8;
                int ncol = wn*64 + (jj*2 + lhi)*8;
                ldsm_x4_t(b[2*jj][0], b[2*jj][1], b[2*jj+1][0], b[2*jj+1][1],
                          bbuf + krow*272 + ncol*2);
            }
            #pragma unroll
            for (int i = 0; i < 2; i++)
                #pragma unroll
                for (int j = 0; j < 8; j++)
                    mma_f16(C[i][j], a[i], b[j]);
        }
    }
    __syncthreads();

    const float* bias = (m0 < EMB) ? (bq + m0) : (bkv + (m0 - EMB));
    const int kind = (m0 < EMB) ? 0 : (m0 < 2*EMB) ? 1 : 2;
    // Q carries 1/sqrt(dk) * log2(e) so softmax can use raw exp2
    const float scale = (kind == 0) ? 0.125f * 1.44269504089f : 1.0f;
    {
        float br[2][2];
        #pragma unroll
        for (int i = 0; i < 2; i++) {
            br[i][0] = bias[wm*32 + i*16 + g];
            br[i][1] = bias[wm*32 + i*16 + g + 8];
        }
        // staging: [t][72] halves (t 0..127, m 0..63), stride 144 B
        #pragma unroll
        for (int i = 0; i < 2; i++)
            #pragma unroll
            for (int j = 0; j < 8; j++)
                #pragma unroll
                for (int v = 0; v < 4; v++) {
                    int ml = wm*32 + i*16 + g + ((v >> 1) << 3);
                    int tl = wn*64 + j*8 + tg*2 + (v & 1);
                    shh[tl*72 + ml] = __float2half_rn((C[i][j][v] + br[i][v>>1]) * scale);
                }
    }
    __syncthreads();

    // store: 128 t x 64 m halves = 1024 uint4 tasks, 8 iters x 128 thr
    #pragma unroll
    for (int r = 0; r < 8; r++) {
        int idx = r*128 + tid;
        int t = idx >> 3, mq = (idx & 7) * 8;
        uint4 w = *(const uint4*)&shh[t*72 + mq];
        int tgl = t0 + t;
        if (kind == 0) {
            int o = m0 + mq, h = o >> 6, d = o & 63;
            *(uint4*)&g_Qh[(((size_t)n*NH + h)*TL + tgl)*DH + d] = w;
        } else if (kind == 1) {
            int oo = m0 - EMB + mq, h = oo >> 6, d = oo & 63;
            *(uint4*)&g_Kh[(((size_t)n*NH + h)*TL + tgl)*DH + d] = w;
        } else {
            int oo = m0 - 2*EMB + mq, h = oo >> 5, d = oo & 31;
            *(uint4*)&g_Vh[(((size_t)n*NH + h)*TL + tgl)*DVH + d] = w;
        }
    }
}

// ---------------------------------------------------------------------------
// Attention (round-13 best, unchanged): cp.async 3-buf K/V pipeline,
// ldmatrix fragments, exp2-domain softmax, Q overlays the KV buffers.
// ---------------------------------------------------------------------------
#define AKV_BYTES 14336
#define AKV_OFF(buf) ((buf)*AKV_BYTES)
#define ATTN_SMEM (3*AKV_BYTES)      // 43008
__global__ __launch_bounds__(128) void attn_mma8()
{
    extern __shared__ __align__(16) unsigned char smraw[];
    const unsigned sbase = (unsigned)__cvta_generic_to_shared(smraw);

    const int qtile = 7 - blockIdx.x;   // heavy tiles first
    const int nh    = blockIdx.y;
    const int tid = threadIdx.x;
    const int wid = tid >> 5, lane = tid & 31;
    const int g = lane >> 2, tg = lane & 3;
    const int r8 = lane & 7, blk = lane >> 3;

    const __half* Qb = g_Qh + ((size_t)nh*TL + qtile*128) * DH;
    const __half* Kb = g_Kh + (size_t)nh*TL*DH;
    const __half* Vb = g_Vh + (size_t)nh*TL*DVH;

    // ---- Q tile into smem (overlaps the future KV buffers) ----
    #pragma unroll
    for (int l = 0; l < 8; l++) {
        int slot = tid + l*128;
        int row = slot >> 3, cc = slot & 7;
        CP16(sbase + row*144 + cc*16, Qb + (size_t)row*DH + cc*8);
    }
    CP_COMMIT();
    CP_WAIT0();
    __syncthreads();

    // ---- Q fragments via ldmatrix ----
    unsigned Aq[2][4][4];
    #pragma unroll
    for (int i = 0; i < 2; i++) {
        const int r0 = wid*32 + i*16;
        #pragma unroll
        for (int ks = 0; ks < 4; ks++) {
            ldsm_x4(Aq[i][ks][0], Aq[i][ks][1], Aq[i][ks][2], Aq[i][ks][3],
                    sbase + (r0 + (blk&1)*8 + r8)*144 + ks*32 + (blk>>1)*16);
        }
    }
    __syncthreads();   // all warps done reading Q -> smem reusable

    auto load_kv = [&](int j, int buf) {
        const unsigned kb_ = sbase + AKV_OFF(buf);
        const unsigned vb_ = kb_ + 9216;
        const __half* Kt = Kb + (size_t)j*64*DH;
        #pragma unroll
        for (int l = 0; l < 4; l++) {
            int slot = tid + l*128;
            int row = slot >> 3, cc = slot & 7;
            CP16(kb_ + row*144 + cc*16, Kt + (size_t)row*DH + cc*8);
        }
        const __half* Vt = Vb + (size_t)j*64*DVH;
        #pragma unroll
        for (int l = 0; l < 2; l++) {
            int slot = tid + l*128;
            int row = slot >> 2, cc = slot & 3;
            CP16(vb_ + row*80 + cc*16, Vt + (size_t)row*DVH + cc*8);
        }
        CP_COMMIT();
    };

    const int jmax = 2*qtile + 1;
    load_kv(0, 0);
    load_kv(1, 1);

    float mr[2][2] = {{-1e30f,-1e30f},{-1e30f,-1e30f}};
    float lr[2][2] = {{0,0},{0,0}};
    float O[2][4][4] = {};

    for (int j = 0; j <= jmax; j++) {
        if (j < jmax) { CP_WAIT1(); } else { CP_WAIT0(); }
        __syncthreads();
        if (j + 2 <= jmax) load_kv(j+2, (j+2) % 3);
        const unsigned kb_ = sbase + AKV_OFF(j % 3);
        const unsigned vb_ = kb_ + 9216;

        // ---- S = Q K^T (log2-domain scores) ----
        float S[2][8][4] = {};
        #pragma unroll
        for (int ks = 0; ks < 4; ks++) {
            unsigned b[8][2];
            #pragma unroll
            for (int np = 0; np < 4; np++) {
                ldsm_x4(b[2*np][0], b[2*np][1], b[2*np+1][0], b[2*np+1][1],
                        kb_ + ((np*2 + (blk>>1))*8 + r8)*144 + ks*32 + (blk&1)*16);
            }
            #pragma unroll
            for (int i = 0; i < 2; i++)
                #pragma unroll
                for (int nt = 0; nt < 8; nt++)
                    mma_f16(S[i][nt], Aq[i][ks], b[nt]);
        }

        // ---- causal mask (near diagonal only) ----
        if (j >= 2*qtile) {
            #pragma unroll
            for (int i = 0; i < 2; i++) {
                const int gr0 = qtile*128 + wid*32 + i*16 + g;
                const int gr1 = gr0 + 8;
                #pragma unroll
                for (int nt = 0; nt < 8; nt++) {
                    const int gc = j*64 + nt*8 + tg*2;
                    if (gc   > gr0) S[i][nt][0] = -1e30f;
                    if (gc+1 > gr0) S[i][nt][1] = -1e30f;
                    if (gc   > gr1) S[i][nt][2] = -1e30f;
                    if (gc+1 > gr1) S[i][nt][3] = -1e30f;
                }
            }
        }

        // ---- online softmax in exp2 domain ----
        #pragma unroll
        for (int i = 0; i < 2; i++) {
            float mx0 = -1e30f, mx1 = -1e30f;
            #pragma unroll
            for (int nt = 0; nt < 8; nt++) {
                mx0 = fmaxf(mx0, fmaxf(S[i][nt][0], S[i][nt][1]));
                mx1 = fmaxf(mx1, fmaxf(S[i][nt][2], S[i][nt][3]));
            }
            mx0 = fmaxf(mx0, __shfl_xor_sync(0xffffffffu, mx0, 1));
            mx0 = fmaxf(mx0, __shfl_xor_sync(0xffffffffu, mx0, 2));
            mx1 = fmaxf(mx1, __shfl_xor_sync(0xffffffffu, mx1, 1));
            mx1 = fmaxf(mx1, __shfl_xor_sync(0xffffffffu, mx1, 2));
            const float mn0 = fmaxf(mr[i][0], mx0), mn1 = fmaxf(mr[i][1], mx1);
            const float al0 = ex2(mr[i][0] - mn0), al1 = ex2(mr[i][1] - mn1);
            float ps0 = 0.0f, ps1 = 0.0f;
            #pragma unroll
            for (int nt = 0; nt < 8; nt++) {
                S[i][nt][0] = ex2(S[i][nt][0] - mn0); ps0 += S[i][nt][0];
                S[i][nt][1] = ex2(S[i][nt][1] - mn0); ps0 += S[i][nt][1];
                S[i][nt][2] = ex2(S[i][nt][2] - mn1); ps1 += S[i][nt][2];
                S[i][nt][3] = ex2(S[i][nt][3] - mn1); ps1 += S[i][nt][3];
            }
            ps0 += __shfl_xor_sync(0xffffffffu, ps0, 1);
            ps0 += __shfl_xor_sync(0xffffffffu, ps0, 2);
            ps1 += __shfl_xor_sync(0xffffffffu, ps1, 1);
            ps1 += __shfl_xor_sync(0xffffffffu, ps1, 2);
            lr[i][0] = lr[i][0]*al0 + ps0;  mr[i][0] = mn0;
            lr[i][1] = lr[i][1]*al1 + ps1;  mr[i][1] = mn1;
            #pragma unroll
            for (int nt = 0; nt < 4; nt++) {
                O[i][nt][0] *= al0; O[i][nt][1] *= al0;
                O[i][nt][2] *= al1; O[i][nt][3] *= al1;
            }
        }

        // ---- O += P V (V b-frags via ldsm.x4.trans, rows = s dim) ----
        #pragma unroll
        for (int kt = 0; kt < 4; kt++) {
            unsigned bv[4][2];
            #pragma unroll
            for (int np = 0; np < 2; np++) {
                ldsm_x4_t(bv[2*np][0], bv[2*np][1], bv[2*np+1][0], bv[2*np+1][1],
                          vb_ + (kt*16 + (blk&1)*8 + r8)*80 + (np*2 + (blk>>1))*16);
            }
            #pragma unroll
            for (int i = 0; i < 2; i++) {
                unsigned a[4];
                a[0] = pack2(S[i][2*kt  ][0], S[i][2*kt  ][1]);
                a[1] = pack2(S[i][2*kt  ][2], S[i][2*kt  ][3]);
                a[2] = pack2(S[i][2*kt+1][0], S[i][2*kt+1][1]);
                a[3] = pack2(S[i][2*kt+1][2], S[i][2*kt+1][3]);
                #pragma unroll
                for (int nt = 0; nt < 4; nt++)
                    mma_f16(O[i][nt], a, bv[nt]);
            }
        }
    }

    // ---- normalize + store to g_Ah interleaved [n][cpair][t][2] ----
    const int n = nh >> 3, h = nh & 7;
    unsigned* gA2 = (unsigned*)g_Ah;
    #pragma unroll
    for (int i = 0; i < 2; i++) {
        const float inv0 = 1.0f / lr[i][0], inv1 = 1.0f / lr[i][1];
        const int t_lo = qtile*128 + wid*32 + i*16 + g;
        const int t_hi = t_lo + 8;
        #pragma unroll
        for (int nt = 0; nt < 4; nt++) {
            int chp = h*16 + nt*4 + tg;
            gA2[((size_t)n*128 + chp)*TL + t_lo] = pack2(O[i][nt][0]*inv0, O[i][nt][1]*inv0);
            gA2[((size_t)n*128 + chp)*TL + t_hi] = pack2(O[i][nt][2]*inv1, O[i][nt][3]*inv1);
        }
    }
}

// ---------------------------------------------------------------------------
// Output projection (round-13 best, unchanged): CTA 128x64, warp 32x32,
// 256 CTAs, direct float2 epilogue.
// ---------------------------------------------------------------------------
#define OPA_BYTES 10240               // A: 128 rows x 80 B
#define OB_BYTES 4608                 // B: 16 * 288
#define OPBUF_BYTES (OPA_BYTES + OB_BYTES)   // 14848
#define OPROJ_SMEM (3*OPBUF_BYTES)    // 44544
__global__ __launch_bounds__(256) void oproj_mma(
    const float* __restrict__ bo, float* __restrict__ out)
{
    extern __shared__ __align__(16) unsigned char smraw[];
    const unsigned sbase = (unsigned)__cvta_generic_to_shared(smraw);

    const int n  = blockIdx.z;
    const int m0 = blockIdx.y * 128;
    const int t0 = blockIdx.x * 64;
    const int tid = threadIdx.x;
    const int wid = tid >> 5, lane = tid & 31;
    const int g = lane >> 2, tg = lane & 3;
    const int wm = wid & 3, wn = wid >> 2;   // warp: rows wm*32, cols wn*32

    const __half* Wsrc = g_Woh + (size_t)m0 * OC;
    const __half* Absrc = g_Ah + (size_t)n * 2*128*TL;   // halves [cpair][t][2]

    float C[2][4][4] = {};

    auto load_chunk = [&](int k0, int buf) {
        const unsigned abuf = sbase + buf*OPBUF_BYTES;
        const unsigned bbuf = abuf + OPA_BYTES;
        #pragma unroll
        for (int l = 0; l < 2; l++) {
            int slot = tid + l*256;
            int m = slot >> 2, cc = slot & 3;
            CP16(abuf + m*80 + cc*16, Wsrc + (size_t)m*OC + k0 + cc*8);
        }
        // B: 16 cpair rows x 256 B/row = 16 tasks/row, 256 total
        {
            int kp = tid >> 4, cc = tid & 15;
            CP16(bbuf + kp*288 + cc*16,
                 Absrc + ((size_t)((k0 >> 1) + kp)*TL + t0 + cc*4)*2);
        }
        CP_COMMIT();
    };

    load_chunk(0, 0);
    load_chunk(32, 1);

    const int lq = (lane >> 3) & 1;
    const int lid8 = lane & 7;
    const int lhi = lane >> 4;

    for (int c = 0; c < 8; c++) {
        if (c < 7) { CP_WAIT1(); } else { CP_WAIT0(); }
        __syncthreads();
        if (c + 2 < 8) load_chunk((c+2)*32, (c+2) % 3);
        const unsigned abuf = sbase + (c % 3)*OPBUF_BYTES;
        const unsigned* B_ = (const unsigned*)(smraw + (c % 3)*OPBUF_BYTES + OPA_BYTES);
        #pragma unroll
        for (int kc = 0; kc < 2; kc++) {
            unsigned a[2][4];
            #pragma unroll
            for (int i = 0; i < 2; i++) {
                int row = wm*32 + i*16 + lq*8 + lid8;
                ldsm_x4(a[i][0], a[i][1], a[i][2], a[i][3],
                        abuf + row*80 + kc*32 + lhi*16);
            }
            unsigned b[4][2];
            #pragma unroll
            for (int j = 0; j < 4; j++) {
                int col = wn*32 + j*8 + g;
                b[j][0] = B_[(kc*8 + tg  )*72 + col];
                b[j][1] = B_[(kc*8 + tg+4)*72 + col];
            }
            #pragma unroll
            for (int i = 0; i < 2; i++)
                #pragma unroll
                for (int j = 0; j < 4; j++)
                    mma_f16(C[i][j], a[i], b[j]);
        }
    }

    // ---- epilogue: direct float2 stores (coalesced 32B per quad-row) ----
    #pragma unroll
    for (int i = 0; i < 2; i++) {
        const int r_lo = m0 + wm*32 + i*16 + g;
        const int r_hi = r_lo + 8;
        const float b_lo = bo[r_lo], b_hi = bo[r_hi];
        #pragma unroll
        for (int j = 0; j < 4; j++) {
            const int tcol = t0 + wn*32 + j*8 + tg*2;
            float2 v0 = { C[i][j][0] + b_lo, C[i][j][1] + b_lo };
            float2 v1 = { C[i][j][2] + b_hi, C[i][j][3] + b_hi };
            *(float2*)(out + ((size_t)n*OC + r_lo)*TL + tcol) = v0;
            *(float2*)(out + ((size_t)n*OC + r_hi)*TL + tcol) = v1;
        }
    }
}

// ---------------------------------------------------------------------------
extern "C" void kernel_launch(void* const* d_in, const int* in_sizes, int n_in,
                              void* d_out, int out_size)
{
    const float* x   = (const float*)d_in[0];
    const float* Wq  = (const float*)d_in[1];
    const float* bq  = (const float*)d_in[2];
    const float* Wkv = (const float*)d_in[3];
    const float* bkv = (const float*)d_in[4];
    const float* Wo  = (const float*)d_in[5];
    const float* bo  = (const float*)d_in[6];
    float* out = (float*)d_out;

    cudaFuncSetAttribute(qkv_mma,
                         cudaFuncAttributeMaxDynamicSharedMemorySize, QKV_SMEM);
    cudaFuncSetAttribute(attn_mma8,
                         cudaFuncAttributeMaxDynamicSharedMemorySize, ATTN_SMEM);
    cudaFuncSetAttribute(oproj_mma,
                         cudaFuncAttributeMaxDynamicSharedMemorySize, OPROJ_SMEM);

    // 0) fp32 -> fp16 conversion
    cvt_inputs<<<1216, 256>>>(Wq, Wkv, x, Wo);

    // 1) QKV: M=1280 (20 tiles of 64), N=1024 (8 tiles of 128), per batch
    qkv_mma<<<dim3(8, 20, NB), 128, QKV_SMEM>>>(bq, bkv);

    // 2) flash attention: 8 Q-tiles of 128 rows, 64 (n,h) pairs
    attn_mma8<<<dim3(8, 64), 128, ATTN_SMEM>>>();

    // 3) O proj: M=256 (2 tiles of 128), N=1024 (16 tiles of 64), per batch
    oproj_mma<<<dim3(16, 2, NB), 256, OPROJ_SMEM>>>(bo, out);
}